// round 13
// baseline (speedup 1.0000x reference)
#include <cuda_runtime.h>
#include <cuda.h>
#include <cstdint>

// ---------------------------------------------------------------------------
// Block-sparse attention prefill (HSA) on tensor cores (mma.sync m16n8k8 tf32),
// with PV(s-1)/QK(s) fusion and consumer-side softmax normalization.
// Per (l, h): for each of S=16 selected 64x128 KV blocks:
//   scores = q . K_blk * sm_scale ; p = softmax_64(scores) * w * valid
//   o += p . V_blk
// B=1, Lq=256, Lkv=4096, HQ=32, H=2, D=128, S=16, BS=64, G=16.
// QK: M=16(g) N=64(u) K=128(d), warps split u (16 each), q A-frags in regs.
// PV: M=16(g) N=128(d) K=64(u), warps split d (32 each).
// Softmax: producers store raw exp + (m,S); consumers rebuild scales.
// ---------------------------------------------------------------------------

__device__ __forceinline__ uint32_t su32(const void* p) {
    return (uint32_t)__cvta_generic_to_shared(p);
}
__device__ __forceinline__ uint32_t tf32cvt(float f) {
    uint32_t r;
    asm("cvt.rna.tf32.f32 %0, %1;" : "=r"(r) : "f"(f));
    return r;
}
__device__ __forceinline__ void mma_tf32(float* c, const uint32_t* a,
                                         uint32_t b0, uint32_t b1) {
    asm volatile(
        "mma.sync.aligned.m16n8k8.row.col.f32.tf32.tf32.f32 "
        "{%0,%1,%2,%3}, {%4,%5,%6,%7}, {%8,%9}, {%0,%1,%2,%3};"
        : "+f"(c[0]), "+f"(c[1]), "+f"(c[2]), "+f"(c[3])
        : "r"(a[0]), "r"(a[1]), "r"(a[2]), "r"(a[3]), "r"(b0), "r"(b1));
}

#define MBAR_INIT(a, c) \
    asm volatile("mbarrier.init.shared.b64 [%0], %1;" :: "r"(a), "r"(c) : "memory")
#define MBAR_EXPECT(a, b) \
    asm volatile("mbarrier.arrive.expect_tx.shared.b64 _, [%0], %1;" :: "r"(a), "r"(b) : "memory")
#define TMA3D(smem, map, x, y, z, mbar) \
    asm volatile("cp.async.bulk.tensor.3d.shared::cta.global.tile.mbarrier::complete_tx::bytes " \
                 "[%0], [%1, {%2, %3, %4}], [%5];" \
                 :: "r"(smem), "l"(map), "r"(x), "r"(y), "r"(z), "r"(mbar) : "memory")

__device__ __forceinline__ void mbar_wait(uint32_t mbar, uint32_t parity) {
    asm volatile(
        "{\n\t.reg .pred P;\n"
        "LW_%=:\n\t"
        "mbarrier.try_wait.parity.acquire.cta.shared::cta.b64 P, [%0], %1, 0x989680;\n\t"
        "@P bra LD_%=;\n\t"
        "bra LW_%=;\n"
        "LD_%=:\n\t}" :: "r"(mbar), "r"(parity) : "memory");
}

namespace hsa {
constexpr int LQ = 256, HQn = 32, Hn = 2, Dn = 128, Sn = 16, BSn = 64, Gn = 16;
constexpr float SM_SCALE = 0.08838834764831845f;  // 1/sqrt(128)

constexpr int TILE_B = 32768;            // 64 rows x 512B = 4 SW128 panels of 8KB
constexpr int KB0    = 0;
constexpr int KB1    = 32768;
constexpr int VB     = 65536;
constexpr int PSTR   = 68;               // P row stride (floats)
constexpr int P_OFF  = 98304;            // 16 x 68 f32 = 4352 B (raw exps)
constexpr int EX_OFF = 102656;           // 16 rows x 4 warps x float2 = 512 B
constexpr int WS_OFF = 103168;           // 256 f32 = 1024 B
constexpr int BI_OFF = 104192;           // 16 int
constexpr int MB_OFF = 104256;           // 3 mbarriers
constexpr int SMEM_BYTES = 104320;       // x2 CTAs = 208640 <= 228KB/SM
}  // namespace hsa
using namespace hsa;

template <bool USE_TMA>
__global__ __launch_bounds__(128, 2)
void hsa_mma(const __grid_constant__ CUtensorMap tmk,
             const __grid_constant__ CUtensorMap tmv,
             const float* __restrict__ q, const float* __restrict__ k,
             const float* __restrict__ v, const float* __restrict__ w,
             const int* __restrict__ bi, float* __restrict__ out)
{
    extern __shared__ char sm[];
    float*  Pb  = (float*)(sm + P_OFF);
    float2* ex  = (float2*)(sm + EX_OFF);
    float*  wsm = (float*)(sm + WS_OFF);
    int*    bis = (int*)(sm + BI_OFF);
    const uint32_t mb = su32(sm + MB_OFF);   // +0: kbar0, +8: kbar1, +16: vbar

    const int h    = blockIdx.x;
    const int l    = blockIdx.y;
    const int tid  = threadIdx.x;
    const int warp = tid >> 5;
    const int lane = tid & 31;
    const int gid  = lane >> 2;      // 0..7
    const int t4   = lane & 3;       // 0..3
    const int r0 = gid, r1 = gid + 8;

    if (USE_TMA && tid == 0) {
        MBAR_INIT(mb + 0, 1);
        MBAR_INIT(mb + 8, 1);
        MBAR_INIT(mb + 16, 1);
    }
    if (tid < 64)
        ((float4*)wsm)[tid] = ((const float4*)(w + (size_t)(l * HQn + h * Gn) * Sn))[tid];
    if (tid < 16)
        bis[tid] = bi[(l * Hn + h) * Sn + tid];
    __syncthreads();

    // --- q A-fragments, tf32, pre-scaled: qa[ks] covers d = 8ks..8ks+7 ---
    uint32_t qa[16][4];
    {
        const float* qb = q + (size_t)(l * HQn + h * Gn) * Dn;
        #pragma unroll
        for (int ks = 0; ks < 16; ++ks) {
            int d0 = 8 * ks;
            qa[ks][0] = tf32cvt(qb[gid * Dn + d0 + t4] * SM_SCALE);
            qa[ks][1] = tf32cvt(qb[(gid + 8) * Dn + d0 + t4] * SM_SCALE);
            qa[ks][2] = tf32cvt(qb[gid * Dn + d0 + t4 + 4] * SM_SCALE);
            qa[ks][3] = tf32cvt(qb[(gid + 8) * Dn + d0 + t4 + 4] * SM_SCALE);
        }
    }

    float oc[4][4];                      // PV accum: 4 n-tiles (d=32w..+31) x 4
    #pragma unroll
    for (int a = 0; a < 4; ++a)
        #pragma unroll
        for (int b = 0; b < 4; ++b) oc[a][b] = 0.0f;

    const int rowa = (16 * warp + gid) * 128;       // QK: K row bases (bytes)
    const int rowb = rowa + 8 * 128;
    const char* vtile = sm + VB + warp * 8192;      // PV: warp's d-panel

    // QK chunk: one k-step (d = 8ks..8ks+7), 2 n-tiles
    const char* kt = sm + KB0;
    float c0[4], c1[4];
    auto qk_ks = [&](int ks) {
        const char* bp = kt + (ks >> 2) * 8192;
        const int cA = ((2 * ks) & 7) ^ gid;
        const int cB = ((2 * ks + 1) & 7) ^ gid;
        uint32_t b0a = *(const uint32_t*)(bp + rowa + (cA << 4) + t4 * 4);
        uint32_t b1a = *(const uint32_t*)(bp + rowa + (cB << 4) + t4 * 4);
        uint32_t b0b = *(const uint32_t*)(bp + rowb + (cA << 4) + t4 * 4);
        uint32_t b1b = *(const uint32_t*)(bp + rowb + (cB << 4) + t4 * 4);
        mma_tf32(c0, qa[ks], b0a, b1a);
        mma_tf32(c1, qa[ks], b0b, b1b);
    };

    // Consumer-side scale: for row, block sblk, from ex + w
    auto make_scl = [&](int sblk, int row, float* scl) {
        float4 xa = *(const float4*)(ex + row * 4);      // (m,S) warps 0,1
        float4 xb = *(const float4*)(ex + row * 4 + 2);  // warps 2,3
        float M = fmaxf(fmaxf(xa.x, xa.z), fmaxf(xb.x, xb.z));
        float t0 = __expf(xa.x - M), t1 = __expf(xa.z - M);
        float t2 = __expf(xb.x - M), t3 = __expf(xb.z - M);
        float G = xa.y * t0 + xa.w * t1 + xb.y * t2 + xb.w * t3;
        float wv = (bis[sblk] >= 0) ? wsm[row * Sn + sblk] : 0.0f;
        float base = __fdividef(wv, G);
        scl[0] = t0 * base; scl[1] = t1 * base;
        scl[2] = t2 * base; scl[3] = t3 * base;
    };

    // PV k-step ku (u = 8ku..8ku+7): A from raw Pb scaled at consume
    float scl0[4], scl1[4];
    auto pv_ku = [&](int ku) {
        int u0 = 8 * ku;
        float2 a02 = *(const float2*)(Pb + gid * PSTR + u0 + 2 * t4);
        float2 a13 = *(const float2*)(Pb + (gid + 8) * PSTR + u0 + 2 * t4);
        const int j = ku >> 1;                 // producer warp of these u
        uint32_t A[4] = {tf32cvt(a02.x * scl0[j]), tf32cvt(a13.x * scl1[j]),
                         tf32cvt(a02.y * scl0[j]), tf32cvt(a13.y * scl1[j])};
        int ua = u0 + 2 * t4;
        int ub = ua + 1;
        int raV = ua * 128 + (gid & 3) * 4;
        int rbV = ub * 128 + (gid & 3) * 4;
        int ua7 = ua & 7, ub7 = ub & 7;
        #pragma unroll
        for (int nt = 0; nt < 4; ++nt) {
            int ch = (2 * nt + (gid >> 2)) & 7;
            uint32_t b0 = *(const uint32_t*)(vtile + raV + ((ch ^ ua7) << 4));
            uint32_t b1 = *(const uint32_t*)(vtile + rbV + ((ch ^ ub7) << 4));
            mma_tf32(oc[nt], A, b0, b1);
        }
    };

    // Softmax partials for block s: per-warp (m,S) + raw exps into Pb
    auto softmax_store = [&]() {
        float m0 = fmaxf(fmaxf(c0[0], c0[1]), fmaxf(c1[0], c1[1]));
        float m1 = fmaxf(fmaxf(c0[2], c0[3]), fmaxf(c1[2], c1[3]));
        m0 = fmaxf(m0, __shfl_xor_sync(0xffffffffu, m0, 1));
        m0 = fmaxf(m0, __shfl_xor_sync(0xffffffffu, m0, 2));
        m1 = fmaxf(m1, __shfl_xor_sync(0xffffffffu, m1, 1));
        m1 = fmaxf(m1, __shfl_xor_sync(0xffffffffu, m1, 2));
        float e00 = __expf(c0[0] - m0), e01 = __expf(c0[1] - m0);
        float e10 = __expf(c1[0] - m0), e11 = __expf(c1[1] - m0);
        float f00 = __expf(c0[2] - m1), f01 = __expf(c0[3] - m1);
        float f10 = __expf(c1[2] - m1), f11 = __expf(c1[3] - m1);
        float S0 = (e00 + e01) + (e10 + e11);
        float S1 = (f00 + f01) + (f10 + f11);
        S0 += __shfl_xor_sync(0xffffffffu, S0, 1);
        S0 += __shfl_xor_sync(0xffffffffu, S0, 2);
        S1 += __shfl_xor_sync(0xffffffffu, S1, 1);
        S1 += __shfl_xor_sync(0xffffffffu, S1, 2);
        if (t4 == 0) {
            ex[r0 * 4 + warp] = make_float2(m0, S0);
            ex[r1 * 4 + warp] = make_float2(m1, S1);
        }
        int cbase = 16 * warp + 2 * t4;
        *(float2*)(Pb + r0 * PSTR + cbase)     = make_float2(e00, e01);
        *(float2*)(Pb + r0 * PSTR + cbase + 8) = make_float2(e10, e11);
        *(float2*)(Pb + r1 * PSTR + cbase)     = make_float2(f00, f01);
        *(float2*)(Pb + r1 * PSTR + cbase + 8) = make_float2(f10, f11);
    };

    if constexpr (USE_TMA) {
        uint32_t kph0 = 0, kph1 = 0, vph = 0;

        // --- Prologue: K(0), K(1), V(0) in flight ---
        if (tid == 0) {
            int b0 = max(bis[0], 0) * BSn;
            int b1 = max(bis[1], 0) * BSn;
            MBAR_EXPECT(mb + 0, TILE_B);
            #pragma unroll
            for (int p = 0; p < 4; ++p)
                TMA3D(su32(sm + KB0 + p * 8192), &tmk, 32 * p, h, b0, mb + 0);
            MBAR_EXPECT(mb + 8, TILE_B);
            #pragma unroll
            for (int p = 0; p < 4; ++p)
                TMA3D(su32(sm + KB1 + p * 8192), &tmk, 32 * p, h, b1, mb + 8);
            MBAR_EXPECT(mb + 16, TILE_B);
            #pragma unroll
            for (int p = 0; p < 4; ++p)
                TMA3D(su32(sm + VB + p * 8192), &tmv, 32 * p, h, b0, mb + 16);
        }

        // --- s = 0: QK only ---
        mbar_wait(mb + 0, kph0); kph0 ^= 1;
        kt = sm + KB0;
        #pragma unroll
        for (int a = 0; a < 4; ++a) { c0[a] = 0.f; c1[a] = 0.f; }
        #pragma unroll
        for (int ks = 0; ks < 16; ++ks) qk_ks(ks);
        softmax_store();
        __syncthreads();                       // ex/Pb(0) visible; QK(0) done

        // --- s = 1..15: fused QK(s) + PV(s-1) ---
        for (int s = 1; s < Sn; ++s) {
            if (tid == 0 && s + 1 < Sn) {      // K(s+1): full-body hiding
                int bn = max(bis[s + 1], 0) * BSn;
                uint32_t kbar = mb + 8u * ((s + 1) & 1);
                char* kdst = sm + (((s + 1) & 1) ? KB1 : KB0);
                MBAR_EXPECT(kbar, TILE_B);
                #pragma unroll
                for (int p = 0; p < 4; ++p)
                    TMA3D(su32(kdst + p * 8192), &tmk, 32 * p, h, bn, kbar);
            }
            if (s & 1) { mbar_wait(mb + 8, kph1); kph1 ^= 1; }
            else       { mbar_wait(mb + 0, kph0); kph0 ^= 1; }
            mbar_wait(mb + 16, vph); vph ^= 1;   // V(s-1)
            kt = sm + ((s & 1) ? KB1 : KB0);

            make_scl(s - 1, r0, scl0);
            make_scl(s - 1, r1, scl1);
            #pragma unroll
            for (int a = 0; a < 4; ++a) { c0[a] = 0.f; c1[a] = 0.f; }

            // fused phase: 6 independent mma chains
            #pragma unroll
            for (int i = 0; i < 8; ++i) {
                qk_ks(2 * i);
                qk_ks(2 * i + 1);
                pv_ku(i);
            }

            __syncthreads();                   // PV(s-1) readers done -> VB free
            if (tid == 0) {                    // V(s) into VB
                int bv = max(bis[s], 0) * BSn;
                MBAR_EXPECT(mb + 16, TILE_B);
                #pragma unroll
                for (int p = 0; p < 4; ++p)
                    TMA3D(su32(sm + VB + p * 8192), &tmv, 32 * p, h, bv, mb + 16);
            }
            softmax_store();
            __syncthreads();                   // ex/Pb(s) visible
        }

        // --- Epilogue: PV(15) ---
        mbar_wait(mb + 16, vph); vph ^= 1;
        make_scl(15, r0, scl0);
        make_scl(15, r1, scl1);
        #pragma unroll
        for (int ku = 0; ku < 8; ++ku) pv_ku(ku);
    } else {
        // Fallback: gather + unfused (correctness path)
        const float4* kb4 = (const float4*)(k + h * Dn);
        const float4* vb4 = (const float4*)(v + h * Dn);
        for (int s = 0; s < Sn; ++s) {
            const int blkc = max(bis[s], 0);
            __syncthreads();
            const float4* krow = kb4 + (size_t)blkc * BSn * 64;
            const float4* vrow = vb4 + (size_t)blkc * BSn * 64;
            #pragma unroll
            for (int j = 0; j < 16; ++j) {
                int c = tid + j * 128;
                int u = c >> 5, d4 = c & 31;
                int panel = d4 >> 3, chunk = d4 & 7;
                int so = panel * 8192 + u * 128 + ((chunk ^ (u & 7)) << 4);
                *(float4*)(sm + KB0 + so) = krow[u * 64 + d4];
                *(float4*)(sm + VB  + so) = vrow[u * 64 + d4];
            }
            __syncthreads();
            kt = sm + KB0;
            #pragma unroll
            for (int a = 0; a < 4; ++a) { c0[a] = 0.f; c1[a] = 0.f; }
            #pragma unroll
            for (int ks = 0; ks < 16; ++ks) qk_ks(ks);
            softmax_store();
            __syncthreads();
            make_scl(s, r0, scl0);
            make_scl(s, r1, scl1);
            #pragma unroll
            for (int ku = 0; ku < 8; ++ku) pv_ku(ku);
        }
    }

    // --- write O: C rows r0/r1, cols d = 32w + 8nt + 2t4 + {0,1} ---
    float* op = out + (size_t)(l * HQn + h * Gn) * Dn;
    #pragma unroll
    for (int nt = 0; nt < 4; ++nt) {
        int d = 32 * warp + 8 * nt + 2 * t4;
        *(float2*)(op + r0 * Dn + d) = make_float2(oc[nt][0], oc[nt][1]);
        *(float2*)(op + r1 * Dn + d) = make_float2(oc[nt][2], oc[nt][3]);
    }
}

// ---------------------------------------------------------------------------
// Host
// ---------------------------------------------------------------------------

typedef CUresult (*EncodeTiled_t)(
    CUtensorMap*, CUtensorMapDataType, cuuint32_t, void*,
    const cuuint64_t*, const cuuint64_t*, const cuuint32_t*, const cuuint32_t*,
    CUtensorMapInterleave, CUtensorMapSwizzle, CUtensorMapL2promotion,
    CUtensorMapFloatOOBfill);

static EncodeTiled_t get_encode_fn() {
    void* fn = nullptr;
    cudaDriverEntryPointQueryResult qr = cudaDriverEntryPointSymbolNotFound;
#if CUDART_VERSION >= 12050
    if (cudaGetDriverEntryPointByVersion("cuTensorMapEncodeTiled", &fn, 12000,
                                         cudaEnableDefault, &qr) != cudaSuccess ||
        qr != cudaDriverEntryPointSuccess)
        fn = nullptr;
#else
    if (cudaGetDriverEntryPoint("cuTensorMapEncodeTiled", &fn,
                                cudaEnableDefault, &qr) != cudaSuccess ||
        qr != cudaDriverEntryPointSuccess)
        fn = nullptr;
#endif
    return (EncodeTiled_t)fn;
}

static bool make_map(EncodeTiled_t enc, CUtensorMap* tm, const void* base) {
    cuuint64_t dims[3]    = {128, 2, 4096};
    cuuint64_t strides[2] = {128ull * 4ull, 256ull * 4ull};
    cuuint32_t box[3]     = {32, 1, 64};
    cuuint32_t estr[3]    = {1, 1, 1};
    CUresult r = enc(tm, CU_TENSOR_MAP_DATA_TYPE_FLOAT32, 3, (void*)base,
                     dims, strides, box, estr,
                     CU_TENSOR_MAP_INTERLEAVE_NONE, CU_TENSOR_MAP_SWIZZLE_128B,
                     CU_TENSOR_MAP_L2_PROMOTION_L2_128B,
                     CU_TENSOR_MAP_FLOAT_OOB_FILL_NONE);
    return r == CUDA_SUCCESS;
}

extern "C" void kernel_launch(void* const* d_in, const int* in_sizes, int n_in,
                              void* d_out, int out_size) {
    const float* q  = (const float*)d_in[0];
    const float* k  = (const float*)d_in[1];
    const float* v  = (const float*)d_in[2];
    const float* w  = (const float*)d_in[3];
    const int*   bi = (const int*)d_in[4];
    float* out = (float*)d_out;

    CUtensorMap tmk, tmv;
    __builtin_memset(&tmk, 0, sizeof(tmk));
    __builtin_memset(&tmv, 0, sizeof(tmv));

    EncodeTiled_t enc = get_encode_fn();
    bool tma_ok = enc && make_map(enc, &tmk, k) && make_map(enc, &tmv, v);

    dim3 grid(Hn, LQ);
    if (tma_ok) {
        cudaFuncSetAttribute(hsa_mma<true>,
                             cudaFuncAttributeMaxDynamicSharedMemorySize, SMEM_BYTES);
        hsa_mma<true><<<grid, 128, SMEM_BYTES>>>(tmk, tmv, q, k, v, w, bi, out);
    } else {
        cudaFuncSetAttribute(hsa_mma<false>,
                             cudaFuncAttributeMaxDynamicSharedMemorySize, SMEM_BYTES);
        hsa_mma<false><<<grid, 128, SMEM_BYTES>>>(tmk, tmv, q, k, v, w, bi, out);
    }
}

// round 14
// speedup vs baseline: 1.0776x; 1.0776x over previous
#include <cuda_runtime.h>
#include <cuda.h>
#include <cstdint>

// ---------------------------------------------------------------------------
// Block-sparse attention prefill (HSA) on tensor cores (mma.sync m16n8k8 tf32).
// 256-thread CTAs (8 warps) for 2x occupancy vs R8; same proven dataflow:
//   per s: [sync] issue V(s),K(s+1); wait K(s); QK; softmax(ex sync);
//          store normalized P; wait V(s); [sync]; PV.
// Per (l, h): for each of S=16 selected 64x128 KV blocks:
//   scores = q . K_blk * sm_scale ; p = softmax_64(scores) * w * valid
//   o += p . V_blk
// B=1, Lq=256, Lkv=4096, HQ=32, H=2, D=128, S=16, BS=64, G=16.
// QK: warps split u (8 each, one m16n8 tile); q tf32 A-frags staged in smem.
// PV: warps split d (16 each, two m16n8 tiles).
// ---------------------------------------------------------------------------

__device__ __forceinline__ uint32_t su32(const void* p) {
    return (uint32_t)__cvta_generic_to_shared(p);
}
__device__ __forceinline__ uint32_t tf32cvt(float f) {
    uint32_t r;
    asm("cvt.rna.tf32.f32 %0, %1;" : "=r"(r) : "f"(f));
    return r;
}
__device__ __forceinline__ void mma_tf32(float* c, const uint32_t* a,
                                         uint32_t b0, uint32_t b1) {
    asm volatile(
        "mma.sync.aligned.m16n8k8.row.col.f32.tf32.tf32.f32 "
        "{%0,%1,%2,%3}, {%4,%5,%6,%7}, {%8,%9}, {%0,%1,%2,%3};"
        : "+f"(c[0]), "+f"(c[1]), "+f"(c[2]), "+f"(c[3])
        : "r"(a[0]), "r"(a[1]), "r"(a[2]), "r"(a[3]), "r"(b0), "r"(b1));
}

#define MBAR_INIT(a, c) \
    asm volatile("mbarrier.init.shared.b64 [%0], %1;" :: "r"(a), "r"(c) : "memory")
#define MBAR_EXPECT(a, b) \
    asm volatile("mbarrier.arrive.expect_tx.shared.b64 _, [%0], %1;" :: "r"(a), "r"(b) : "memory")
#define TMA3D(smem, map, x, y, z, mbar) \
    asm volatile("cp.async.bulk.tensor.3d.shared::cta.global.tile.mbarrier::complete_tx::bytes " \
                 "[%0], [%1, {%2, %3, %4}], [%5];" \
                 :: "r"(smem), "l"(map), "r"(x), "r"(y), "r"(z), "r"(mbar) : "memory")

__device__ __forceinline__ void mbar_wait(uint32_t mbar, uint32_t parity) {
    asm volatile(
        "{\n\t.reg .pred P;\n"
        "LW_%=:\n\t"
        "mbarrier.try_wait.parity.acquire.cta.shared::cta.b64 P, [%0], %1, 0x989680;\n\t"
        "@P bra LD_%=;\n\t"
        "bra LW_%=;\n"
        "LD_%=:\n\t}" :: "r"(mbar), "r"(parity) : "memory");
}

namespace hsa {
constexpr int LQ = 256, HQn = 32, Hn = 2, Dn = 128, Sn = 16, BSn = 64, Gn = 16;
constexpr float SM_SCALE = 0.08838834764831845f;  // 1/sqrt(128)

constexpr int TILE_B = 32768;            // 64 rows x 512B = 4 SW128 panels of 8KB
constexpr int KB0    = 0;
constexpr int KB1    = 32768;
constexpr int VB     = 65536;
constexpr int QA_OFF = 98304;            // 16ks x 32lane x 4 tf32 = 8192 B
constexpr int PSTR   = 68;               // P row stride (floats)
constexpr int P_OFF  = 106496;           // 16 x 68 f32 = 4352 B
constexpr int EXSTR  = 80;               // ex row stride (bytes): 8 warps x f2 + pad
constexpr int EX_OFF = 110848;           // 16 x 80 = 1280 B
constexpr int WS_OFF = 112128;           // 256 f32 = 1024 B
constexpr int BI_OFF = 113152;           // 16 int
constexpr int MB_OFF = 113216;           // 3 mbarriers
constexpr int SMEM_BYTES = 113280;       // x2 CTAs = 226560 (<= 231680 proven)
}  // namespace hsa
using namespace hsa;

template <bool USE_TMA>
__global__ __launch_bounds__(256, 2)
void hsa_mma(const __grid_constant__ CUtensorMap tmk,
             const __grid_constant__ CUtensorMap tmv,
             const float* __restrict__ q, const float* __restrict__ k,
             const float* __restrict__ v, const float* __restrict__ w,
             const int* __restrict__ bi, float* __restrict__ out)
{
    extern __shared__ char sm[];
    uint32_t* qa_s = (uint32_t*)(sm + QA_OFF);
    float*    Pb   = (float*)(sm + P_OFF);
    char*     exb  = sm + EX_OFF;
    float*    wsm  = (float*)(sm + WS_OFF);
    int*      bis  = (int*)(sm + BI_OFF);
    const uint32_t mb = su32(sm + MB_OFF);   // +0: kbar0, +8: kbar1, +16: vbar

    const int h    = blockIdx.x;
    const int l    = blockIdx.y;
    const int tid  = threadIdx.x;
    const int warp = tid >> 5;       // 0..7
    const int lane = tid & 31;
    const int gid  = lane >> 2;      // 0..7
    const int t4   = lane & 3;       // 0..3
    const int r0 = gid, r1 = gid + 8;

    if (USE_TMA && tid == 0) {
        MBAR_INIT(mb + 0, 1);
        MBAR_INIT(mb + 8, 1);
        MBAR_INIT(mb + 16, 1);
    }
    // --- stage w, block indices, q A-fragments (tf32, pre-scaled) ---
    if (tid < 64)
        ((float4*)wsm)[tid] = ((const float4*)(w + (size_t)(l * HQn + h * Gn) * Sn))[tid];
    if (tid < 16)
        bis[tid] = bi[(l * Hn + h) * Sn + tid];
    {
        const float* qb = q + (size_t)(l * HQn + h * Gn) * Dn;
        #pragma unroll
        for (int i = tid; i < 512; i += 256) {     // slot = ks*32 + lane
            int ks = i >> 5, lp = i & 31;
            int g = lp >> 2, tt = lp & 3;
            int d0 = 8 * ks;
            uint32_t* dst = qa_s + i * 4;
            dst[0] = tf32cvt(qb[g * Dn + d0 + tt] * SM_SCALE);
            dst[1] = tf32cvt(qb[(g + 8) * Dn + d0 + tt] * SM_SCALE);
            dst[2] = tf32cvt(qb[g * Dn + d0 + tt + 4] * SM_SCALE);
            dst[3] = tf32cvt(qb[(g + 8) * Dn + d0 + tt + 4] * SM_SCALE);
        }
    }
    __syncthreads();

    if (USE_TMA && tid == 0) {       // prologue: K(0)
        int b0 = max(bis[0], 0) * BSn;
        MBAR_EXPECT(mb + 0, TILE_B);
        #pragma unroll
        for (int p = 0; p < 4; ++p)
            TMA3D(su32(sm + KB0 + p * 8192), &tmk, 32 * p, h, b0, mb + 0);
    }

    float oc[2][4];                  // PV accum: 2 n-tiles (d = 16w + 8nt + ..)
    #pragma unroll
    for (int a = 0; a < 2; ++a)
        #pragma unroll
        for (int b = 0; b < 4; ++b) oc[a][b] = 0.0f;

    const int rowA = (8 * warp + gid) * 128;     // QK: K row base (bytes), row&7==gid
    const char* vp = sm + VB + (warp >> 1) * 8192;   // PV: warp's 32-d panel
    const int vhalf = 4 * (warp & 1);                // 16-d half within panel

    const char* kt = sm + KB0;
    float c[4];

    auto qk_ks = [&](int ks) {
        uint4 a = *(const uint4*)(qa_s + (ks * 32 + lane) * 4);
        const char* bp = kt + (ks >> 2) * 8192;
        int cA = ((2 * ks) & 7) ^ gid;
        int cB = ((2 * ks + 1) & 7) ^ gid;
        uint32_t b0 = *(const uint32_t*)(bp + rowA + (cA << 4) + t4 * 4);
        uint32_t b1 = *(const uint32_t*)(bp + rowA + (cB << 4) + t4 * 4);
        mma_tf32(c, (const uint32_t*)&a, b0, b1);
    };

    auto pv_ku = [&](int ku) {
        int u0 = 8 * ku;
        float2 a02 = *(const float2*)(Pb + gid * PSTR + u0 + 2 * t4);
        float2 a13 = *(const float2*)(Pb + (gid + 8) * PSTR + u0 + 2 * t4);
        uint32_t A[4] = {__float_as_uint(a02.x), __float_as_uint(a13.x),
                         __float_as_uint(a02.y), __float_as_uint(a13.y)};
        int ua = u0 + 2 * t4;
        int ub = ua + 1;
        int raV = ua * 128 + (gid & 3) * 4;
        int rbV = ub * 128 + (gid & 3) * 4;
        int ua7 = ua & 7, ub7 = ub & 7;
        #pragma unroll
        for (int nt = 0; nt < 2; ++nt) {
            int ch = (vhalf + 2 * nt + (gid >> 2)) & 7;
            uint32_t b0 = *(const uint32_t*)(vp + raV + ((ch ^ ua7) << 4));
            uint32_t b1 = *(const uint32_t*)(vp + rbV + ((ch ^ ub7) << 4));
            mma_tf32(oc[nt], A, b0, b1);
        }
    };

    // Softmax for block s: partial (8 u per warp) -> ex -> sync -> combine ->
    // store normalized tf32 P rows.
    auto softmax_part1 = [&](float& m0, float& m1, float& e0, float& e1,
                             float& f0, float& f1) {
        m0 = fmaxf(c[0], c[1]);
        m1 = fmaxf(c[2], c[3]);
        m0 = fmaxf(m0, __shfl_xor_sync(0xffffffffu, m0, 1));
        m0 = fmaxf(m0, __shfl_xor_sync(0xffffffffu, m0, 2));
        m1 = fmaxf(m1, __shfl_xor_sync(0xffffffffu, m1, 1));
        m1 = fmaxf(m1, __shfl_xor_sync(0xffffffffu, m1, 2));
        e0 = __expf(c[0] - m0); e1 = __expf(c[1] - m0);
        f0 = __expf(c[2] - m1); f1 = __expf(c[3] - m1);
        float S0 = e0 + e1;
        float S1 = f0 + f1;
        S0 += __shfl_xor_sync(0xffffffffu, S0, 1);
        S0 += __shfl_xor_sync(0xffffffffu, S0, 2);
        S1 += __shfl_xor_sync(0xffffffffu, S1, 1);
        S1 += __shfl_xor_sync(0xffffffffu, S1, 2);
        if (t4 == 0) {
            *(float2*)(exb + r0 * EXSTR + warp * 8) = make_float2(m0, S0);
            *(float2*)(exb + r1 * EXSTR + warp * 8) = make_float2(m1, S1);
        }
    };
    auto combine_row = [&](int row, float mwarp, float wv) -> float {
        float4 x = *(const float4*)(exb + row * EXSTR + t4 * 16);  // (m,S)x2
        float ml = fmaxf(x.x, x.z);
        ml = fmaxf(ml, __shfl_xor_sync(0xffffffffu, ml, 1));
        ml = fmaxf(ml, __shfl_xor_sync(0xffffffffu, ml, 2));
        float g = x.y * __expf(x.x - ml) + x.w * __expf(x.z - ml);
        g += __shfl_xor_sync(0xffffffffu, g, 1);
        g += __shfl_xor_sync(0xffffffffu, g, 2);
        return __expf(mwarp - ml) * __fdividef(wv, g);
    };

    uint32_t kph0 = 0, kph1 = 0, vph = 0;
    const float4* kb4 = (const float4*)(k + h * Dn);
    const float4* vb4 = (const float4*)(v + h * Dn);

    for (int s = 0; s < Sn; ++s) {
        const int blkraw = bis[s];
        const int blkc   = max(blkraw, 0);

        __syncthreads();   // prev iter's PV readers done (VB free); K buf free

        if constexpr (USE_TMA) {
            if (tid == 0) {
                MBAR_EXPECT(mb + 16, TILE_B);
                #pragma unroll
                for (int p = 0; p < 4; ++p)
                    TMA3D(su32(sm + VB + p * 8192), &tmv, 32 * p, h, blkc * BSn, mb + 16);
                if (s + 1 < Sn) {
                    int bn = max(bis[s + 1], 0) * BSn;
                    uint32_t kbar = mb + 8u * ((s + 1) & 1);
                    char* kdst = sm + (((s + 1) & 1) ? KB1 : KB0);
                    MBAR_EXPECT(kbar, TILE_B);
                    #pragma unroll
                    for (int p = 0; p < 4; ++p)
                        TMA3D(su32(kdst + p * 8192), &tmk, 32 * p, h, bn, kbar);
                }
            }
            if (s & 1) { mbar_wait(mb + 8, kph1); kph1 ^= 1; }
            else       { mbar_wait(mb + 0, kph0); kph0 ^= 1; }
            kt = sm + ((s & 1) ? KB1 : KB0);
        } else {
            // fallback gather: LDG -> SW128-swizzled STS (256 threads)
            const float4* krow = kb4 + (size_t)blkc * BSn * 64;
            const float4* vrow = vb4 + (size_t)blkc * BSn * 64;
            #pragma unroll
            for (int j = 0; j < 8; ++j) {
                int cidx = tid + j * 256;
                int u = cidx >> 5, d4 = cidx & 31;
                int panel = d4 >> 3, chunk = d4 & 7;
                int so = panel * 8192 + u * 128 + ((chunk ^ (u & 7)) << 4);
                *(float4*)(sm + KB0 + so) = krow[u * 64 + d4];
                *(float4*)(sm + VB  + so) = vrow[u * 64 + d4];
            }
            __syncthreads();
            kt = sm + KB0;
        }

        // --- QK: warp's 8 keys (u = 8w..8w+7), 16 k-steps ---
        #pragma unroll
        for (int a = 0; a < 4; ++a) c[a] = 0.0f;
        #pragma unroll
        for (int ks = 0; ks < 16; ++ks) qk_ks(ks);

        // --- softmax ---
        float m0, m1, e0, e1, f0, f1;
        softmax_part1(m0, m1, e0, e1, f0, f1);
        __syncthreads();                       // ex visible
        float wv0 = (blkraw >= 0) ? wsm[r0 * Sn + s] : 0.0f;
        float wv1 = (blkraw >= 0) ? wsm[r1 * Sn + s] : 0.0f;
        float scl0 = combine_row(r0, m0, wv0);
        float scl1 = combine_row(r1, m1, wv1);
        {
            int cb = 8 * warp + 2 * t4;
            uint32_t p00 = tf32cvt(e0 * scl0), p01 = tf32cvt(e1 * scl0);
            uint32_t p10 = tf32cvt(f0 * scl1), p11 = tf32cvt(f1 * scl1);
            *(uint2*)(Pb + r0 * PSTR + cb) = make_uint2(p00, p01);
            *(uint2*)(Pb + r1 * PSTR + cb) = make_uint2(p10, p11);
        }

        if constexpr (USE_TMA) { mbar_wait(mb + 16, vph); vph ^= 1; }
        __syncthreads();                       // P visible; V resident

        // --- PV: warp's 16 dims (d = 16w..16w+15), 8 k-steps x 2 n-tiles ---
        #pragma unroll
        for (int ku = 0; ku < 8; ++ku) pv_ku(ku);
    }

    // --- write O: rows r0/r1, cols d = 16w + 8nt + 2t4 + {0,1} ---
    float* op = out + (size_t)(l * HQn + h * Gn) * Dn;
    #pragma unroll
    for (int nt = 0; nt < 2; ++nt) {
        int d = 16 * warp + 8 * nt + 2 * t4;
        *(float2*)(op + r0 * Dn + d) = make_float2(oc[nt][0], oc[nt][1]);
        *(float2*)(op + r1 * Dn + d) = make_float2(oc[nt][2], oc[nt][3]);
    }
}

// ---------------------------------------------------------------------------
// Host
// ---------------------------------------------------------------------------

typedef CUresult (*EncodeTiled_t)(
    CUtensorMap*, CUtensorMapDataType, cuuint32_t, void*,
    const cuuint64_t*, const cuuint64_t*, const cuuint32_t*, const cuuint32_t*,
    CUtensorMapInterleave, CUtensorMapSwizzle, CUtensorMapL2promotion,
    CUtensorMapFloatOOBfill);

static EncodeTiled_t get_encode_fn() {
    void* fn = nullptr;
    cudaDriverEntryPointQueryResult qr = cudaDriverEntryPointSymbolNotFound;
#if CUDART_VERSION >= 12050
    if (cudaGetDriverEntryPointByVersion("cuTensorMapEncodeTiled", &fn, 12000,
                                         cudaEnableDefault, &qr) != cudaSuccess ||
        qr != cudaDriverEntryPointSuccess)
        fn = nullptr;
#else
    if (cudaGetDriverEntryPoint("cuTensorMapEncodeTiled", &fn,
                                cudaEnableDefault, &qr) != cudaSuccess ||
        qr != cudaDriverEntryPointSuccess)
        fn = nullptr;
#endif
    return (EncodeTiled_t)fn;
}

static bool make_map(EncodeTiled_t enc, CUtensorMap* tm, const void* base) {
    cuuint64_t dims[3]    = {128, 2, 4096};
    cuuint64_t strides[2] = {128ull * 4ull, 256ull * 4ull};
    cuuint32_t box[3]     = {32, 1, 64};
    cuuint32_t estr[3]    = {1, 1, 1};
    CUresult r = enc(tm, CU_TENSOR_MAP_DATA_TYPE_FLOAT32, 3, (void*)base,
                     dims, strides, box, estr,
                     CU_TENSOR_MAP_INTERLEAVE_NONE, CU_TENSOR_MAP_SWIZZLE_128B,
                     CU_TENSOR_MAP_L2_PROMOTION_L2_128B,
                     CU_TENSOR_MAP_FLOAT_OOB_FILL_NONE);
    return r == CUDA_SUCCESS;
}

extern "C" void kernel_launch(void* const* d_in, const int* in_sizes, int n_in,
                              void* d_out, int out_size) {
    const float* q  = (const float*)d_in[0];
    const float* k  = (const float*)d_in[1];
    const float* v  = (const float*)d_in[2];
    const float* w  = (const float*)d_in[3];
    const int*   bi = (const int*)d_in[4];
    float* out = (float*)d_out;

    CUtensorMap tmk, tmv;
    __builtin_memset(&tmk, 0, sizeof(tmk));
    __builtin_memset(&tmv, 0, sizeof(tmv));

    EncodeTiled_t enc = get_encode_fn();
    bool tma_ok = enc && make_map(enc, &tmk, k) && make_map(enc, &tmv, v);

    dim3 grid(Hn, LQ);
    if (tma_ok) {
        cudaFuncSetAttribute(hsa_mma<true>,
                             cudaFuncAttributeMaxDynamicSharedMemorySize, SMEM_BYTES);
        hsa_mma<true><<<grid, 256, SMEM_BYTES>>>(tmk, tmv, q, k, v, w, bi, out);
    } else {
        cudaFuncSetAttribute(hsa_mma<false>,
                             cudaFuncAttributeMaxDynamicSharedMemorySize, SMEM_BYTES);
        hsa_mma<false><<<grid, 256, SMEM_BYTES>>>(tmk, tmv, q, k, v, w, bi, out);
    }
}